// round 11
// baseline (speedup 1.0000x reference)
#include <cuda_runtime.h>
#include <stdint.h>
#include <math.h>

#define BATCH 2
#define TSEQ  2048
#define NHEAD 12
#define HDIM  64
#define CEMB  768
#define C3    (3 * CEMB)

__device__ float g_qkv[BATCH * TSEQ * C3];    // 36 MB (tf32-rounded values)
__device__ float g_y[BATCH * TSEQ * CEMB];    // 12 MB (tf32-rounded values)
__device__ float g_xr[BATCH * TSEQ * CEMB];   // rounded x
__device__ float g_war[CEMB * C3];            // rounded W_attn
__device__ float g_wpr[CEMB * CEMB];          // rounded W_proj

__device__ __forceinline__ uint32_t f2tf(float x) {
  uint32_t r;
  asm("cvt.rna.tf32.f32 %0, %1;" : "=r"(r) : "f"(x));
  return r;
}
__device__ __forceinline__ float4 tf4(float4 v) {
  v.x = __uint_as_float(f2tf(v.x));
  v.y = __uint_as_float(f2tf(v.y));
  v.z = __uint_as_float(f2tf(v.z));
  v.w = __uint_as_float(f2tf(v.w));
  return v;
}
__device__ __forceinline__ uint32_t fu(float x) { return __float_as_uint(x); }

__device__ __forceinline__ void mma8(float* c, uint32_t a0, uint32_t a1,
                                     uint32_t a2, uint32_t a3,
                                     uint32_t b0, uint32_t b1) {
  asm volatile(
      "mma.sync.aligned.m16n8k8.row.col.f32.tf32.tf32.f32 "
      "{%0,%1,%2,%3}, {%4,%5,%6,%7}, {%8,%9}, {%0,%1,%2,%3};\n"
      : "+f"(c[0]), "+f"(c[1]), "+f"(c[2]), "+f"(c[3])
      : "r"(a0), "r"(a1), "r"(a2), "r"(a3), "r"(b0), "r"(b1));
}

__device__ __forceinline__ void cpa16(void* s, const void* g) {
  uint32_t sa = (uint32_t)__cvta_generic_to_shared(s);
  asm volatile("cp.async.cg.shared.global [%0], [%1], 16;\n" ::"r"(sa), "l"(g));
}
#define CP_COMMIT() asm volatile("cp.async.commit_group;\n")
#define CP_WAIT(n)  asm volatile("cp.async.wait_group %0;\n" ::"n"(n))

// ---------------------------------------------------------------------------
// Elementwise rna-round to tf32 pre-pass
// ---------------------------------------------------------------------------
__global__ __launch_bounds__(256) void round_tf32(const float* __restrict__ in,
                                                  float* __restrict__ out,
                                                  int n4) {
  int i = blockIdx.x * 256 + threadIdx.x;
  if (i < n4) *(float4*)&out[i * 4] = tf4(*(const float4*)&in[i * 4]);
}

// ---------------------------------------------------------------------------
// tf32 GEMM, 4-stage cp.async. CTA tile 128x128, 4 warps, warp tile 64x64
// (acc reuse: 16 FLOP per smem byte -> crossbar no longer caps tensor).
// BK=16. Operands pre-rounded. 128 threads, 2 CTAs/SM (256 regs available).
// ---------------------------------------------------------------------------
#define APITCH 20    // A-frag banks (20r+q) mod 32 all unique
#define BPITCH 136   // B-frag banks (8q+r) all unique
#define ABUF (128 * APITCH)
#define BBUF (16 * BPITCH)
#define GSTAGES 4
#define GEMM_SMEM (GSTAGES * (ABUF + BBUF) * sizeof(float))  // 75776 B

template <bool ROUND_OUT>
__global__ __launch_bounds__(128, 2) void gemm_tf32(
    const float* __restrict__ A, const float* __restrict__ B,
    const float* __restrict__ bias, float* __restrict__ C, int N, int K) {
  extern __shared__ float sm[];
  float* As = sm;
  float* Bs = sm + GSTAGES * ABUF;

  const int tid = threadIdx.x;
  const int warp = tid >> 5, lane = tid & 31;
  const int r = lane >> 2, q = lane & 3;
  const int wm = (warp >> 1) * 64, wn = (warp & 1) * 64;
  const int bm = blockIdx.y * 128, bn = blockIdx.x * 128;

  // A: 128x16 via 4 cpa16/thread: rows ar+{0,32,64,96}, col ac
  const int ar = tid >> 2, ac = (tid & 3) * 4;
  // B: 16x128 via 4 cpa16/thread: rows br+{0,4,8,12}, col bc
  const int br = tid >> 5, bc = (tid & 31) * 4;
  const float* Ag = A + (size_t)(bm + ar) * K + ac;
  const float* Bg = B + (size_t)br * N + bn + bc;

  float acc[4][8][4];
#pragma unroll
  for (int i = 0; i < 4; i++)
#pragma unroll
    for (int j = 0; j < 8; j++)
#pragma unroll
      for (int t = 0; t < 4; t++) acc[i][j][t] = 0.0f;

  const int nk = K / 16;

#pragma unroll
  for (int i = 0; i < GSTAGES - 1; i++) {
    if (i < nk) {
      float* Ad = As + i * ABUF;
      float* Bd = Bs + i * BBUF;
      const float* Agk = Ag + i * 16;
      const float* Bgk = Bg + (size_t)i * 16 * N;
#pragma unroll
      for (int j = 0; j < 4; j++)
        cpa16(&Ad[(ar + j * 32) * APITCH + ac], Agk + (size_t)j * 32 * K);
#pragma unroll
      for (int j = 0; j < 4; j++)
        cpa16(&Bd[(br + j * 4) * BPITCH + bc], Bgk + (size_t)j * 4 * N);
    }
    CP_COMMIT();
  }
  CP_WAIT(2);
  __syncthreads();

  for (int kb = 0; kb < nk; kb++) {
    const float* Ac = As + (kb & 3) * ABUF;
    const float* Bc = Bs + (kb & 3) * BBUF;
#pragma unroll
    for (int ks = 0; ks < 2; ks++) {
      const int k0 = ks * 8;
      uint32_t af[4][4];
#pragma unroll
      for (int mt = 0; mt < 4; mt++) {
        const float* ap = &Ac[(wm + mt * 16) * APITCH + k0];
        af[mt][0] = fu(ap[r * APITCH + q]);
        af[mt][1] = fu(ap[(r + 8) * APITCH + q]);
        af[mt][2] = fu(ap[r * APITCH + q + 4]);
        af[mt][3] = fu(ap[(r + 8) * APITCH + q + 4]);
      }
#pragma unroll
      for (int nt = 0; nt < 8; nt++) {
        uint32_t b0 = fu(Bc[(k0 + q) * BPITCH + wn + nt * 8 + r]);
        uint32_t b1 = fu(Bc[(k0 + q + 4) * BPITCH + wn + nt * 8 + r]);
#pragma unroll
        for (int mt = 0; mt < 4; mt++)
          mma8(acc[mt][nt], af[mt][0], af[mt][1], af[mt][2], af[mt][3], b0, b1);
      }
    }

    if (kb + 3 < nk) {
      int st = (kb + 3) & 3;
      float* Ad = As + st * ABUF;
      float* Bd = Bs + st * BBUF;
      const float* Agk = Ag + (kb + 3) * 16;
      const float* Bgk = Bg + (size_t)(kb + 3) * 16 * N;
#pragma unroll
      for (int j = 0; j < 4; j++)
        cpa16(&Ad[(ar + j * 32) * APITCH + ac], Agk + (size_t)j * 32 * K);
#pragma unroll
      for (int j = 0; j < 4; j++)
        cpa16(&Bd[(br + j * 4) * BPITCH + bc], Bgk + (size_t)j * 4 * N);
    }
    CP_COMMIT();
    CP_WAIT(2);
    __syncthreads();
  }

#pragma unroll
  for (int mt = 0; mt < 4; mt++) {
    int row_lo = bm + wm + mt * 16 + r;
#pragma unroll
    for (int nt = 0; nt < 8; nt++) {
      int col = bn + wn + nt * 8 + 2 * q;
      float2 bv = *(const float2*)&bias[col];
      float2 o0 = make_float2(acc[mt][nt][0] + bv.x, acc[mt][nt][1] + bv.y);
      float2 o1 = make_float2(acc[mt][nt][2] + bv.x, acc[mt][nt][3] + bv.y);
      if (ROUND_OUT) {
        o0.x = __uint_as_float(f2tf(o0.x));
        o0.y = __uint_as_float(f2tf(o0.y));
        o1.x = __uint_as_float(f2tf(o1.x));
        o1.y = __uint_as_float(f2tf(o1.y));
      }
      *(float2*)&C[(size_t)row_lo * N + col] = o0;
      *(float2*)&C[(size_t)(row_lo + 8) * N + col] = o1;
    }
  }
}

// ---------------------------------------------------------------------------
// Flash attention (unchanged from R8: 64q/CTA, 4 warps, 3 CTAs/SM,
// K double-buf, V single-buf, VPITCH=72 conflict-free PV loads).
// ---------------------------------------------------------------------------
#define PITCH 68
#define VPITCH 72
#define VS_OFF (2 * 64 * PITCH)
#define PS_OFF (VS_OFF + 64 * VPITCH)
#define ATT_SMEM ((PS_OFF + 64 * PITCH) * sizeof(float))  // 70656 B

__global__ __launch_bounds__(128, 3) void attn_tf32() {
  extern __shared__ float sm[];
  float* Kb0 = sm;
  float* Kb1 = sm + 64 * PITCH;
  float* Vs  = sm + VS_OFF;
  float* Ps  = sm + PS_OFF;

  const int tid = threadIdx.x;
  const int warp = tid >> 5, lane = tid & 31;
  const int r = lane >> 2, q = lane & 3;
  const int qb = 31 - blockIdx.x;
  const int bh = blockIdx.y;
  const int b = bh / NHEAD, h = bh % NHEAD;
  const int q0 = qb * 64;
  const float* qkv = g_qkv + (size_t)b * TSEQ * C3 + h * HDIM;

  const int rbase = tid >> 4;
  const int d4 = (tid & 15) << 2;

#pragma unroll
  for (int j = 0; j < 8; j++) {
    int rr = rbase + j * 8;
    float4 v = *(const float4*)&qkv[(size_t)(q0 + rr) * C3 + d4];
    v.x *= 0.125f; v.y *= 0.125f; v.z *= 0.125f; v.w *= 0.125f;
    *(float4*)&Ps[rr * PITCH + d4] = v;
  }
  {
    const float* kg = &qkv[(size_t)rbase * C3 + CEMB + d4];
#pragma unroll
    for (int j = 0; j < 8; j++)
      cpa16(&Kb0[(rbase + j * 8) * PITCH + d4], kg + (size_t)j * 8 * C3);
    CP_COMMIT();
  }
  __syncthreads();

  uint32_t qf[8][4];
  const int wr = warp * 16;
#pragma unroll
  for (int ks = 0; ks < 8; ks++) {
    const float* ap = &Ps[wr * PITCH + ks * 8];
    qf[ks][0] = fu(ap[r * PITCH + q]);
    qf[ks][1] = fu(ap[(r + 8) * PITCH + q]);
    qf[ks][2] = fu(ap[r * PITCH + q + 4]);
    qf[ks][3] = fu(ap[(r + 8) * PITCH + q + 4]);
  }
  __syncthreads();

  float m_lo = -1e30f, m_hi = -1e30f, l_lo = 0.0f, l_hi = 0.0f;
  float o[8][4];
#pragma unroll
  for (int nt = 0; nt < 8; nt++)
#pragma unroll
    for (int t = 0; t < 4; t++) o[nt][t] = 0.0f;

  for (int kb = 0; kb <= qb; kb++) {
    {
      const float* vg = &qkv[(size_t)(kb * 64 + rbase) * C3 + 2 * CEMB + d4];
#pragma unroll
      for (int j = 0; j < 8; j++)
        cpa16(&Vs[(rbase + j * 8) * VPITCH + d4], vg + (size_t)j * 8 * C3);
      CP_COMMIT();
    }
    if (kb < qb) {
      float* Kn = (kb & 1) ? Kb0 : Kb1;
      const float* kg = &qkv[(size_t)((kb + 1) * 64 + rbase) * C3 + CEMB + d4];
#pragma unroll
      for (int j = 0; j < 8; j++)
        cpa16(&Kn[(rbase + j * 8) * PITCH + d4], kg + (size_t)j * 8 * C3);
    }
    CP_COMMIT();

    CP_WAIT(2);
    __syncthreads();

    const float* Kc = (kb & 1) ? Kb1 : Kb0;

    float s[8][4];
#pragma unroll
    for (int nt = 0; nt < 8; nt++)
#pragma unroll
      for (int t = 0; t < 4; t++) s[nt][t] = 0.0f;
#pragma unroll
    for (int ks = 0; ks < 8; ks++) {
#pragma unroll
      for (int nt = 0; nt < 8; nt++) {
        uint32_t b0 = fu(Kc[(nt * 8 + r) * PITCH + ks * 8 + q]);
        uint32_t b1 = fu(Kc[(nt * 8 + r) * PITCH + ks * 8 + q + 4]);
        mma8(s[nt], qf[ks][0], qf[ks][1], qf[ks][2], qf[ks][3], b0, b1);
      }
    }

    if (kb == qb) {
      const int row_lo = wr + r, row_hi = row_lo + 8;
#pragma unroll
      for (int nt = 0; nt < 8; nt++) {
        int col = nt * 8 + 2 * q;
        if (col > row_lo) s[nt][0] = -1e30f;
        if (col + 1 > row_lo) s[nt][1] = -1e30f;
        if (col > row_hi) s[nt][2] = -1e30f;
        if (col + 1 > row_hi) s[nt][3] = -1e30f;
      }
    }

    float mx_lo = s[0][0], mx_hi = s[0][2];
#pragma unroll
    for (int nt = 0; nt < 8; nt++) {
      mx_lo = fmaxf(mx_lo, fmaxf(s[nt][0], s[nt][1]));
      mx_hi = fmaxf(mx_hi, fmaxf(s[nt][2], s[nt][3]));
    }
    mx_lo = fmaxf(mx_lo, __shfl_xor_sync(0xffffffffu, mx_lo, 1));
    mx_lo = fmaxf(mx_lo, __shfl_xor_sync(0xffffffffu, mx_lo, 2));
    mx_hi = fmaxf(mx_hi, __shfl_xor_sync(0xffffffffu, mx_hi, 1));
    mx_hi = fmaxf(mx_hi, __shfl_xor_sync(0xffffffffu, mx_hi, 2));

    float mn_lo = fmaxf(m_lo, mx_lo), mn_hi = fmaxf(m_hi, mx_hi);
    float corr_lo = __expf(m_lo - mn_lo), corr_hi = __expf(m_hi - mn_hi);

    float ls_lo = 0.0f, ls_hi = 0.0f;
#pragma unroll
    for (int nt = 0; nt < 8; nt++) {
      int col = nt * 8 + 2 * q;
      float p0 = __uint_as_float(f2tf(__expf(s[nt][0] - mn_lo)));
      float p1 = __uint_as_float(f2tf(__expf(s[nt][1] - mn_lo)));
      float p2 = __uint_as_float(f2tf(__expf(s[nt][2] - mn_hi)));
      float p3 = __uint_as_float(f2tf(__expf(s[nt][3] - mn_hi)));
      ls_lo += p0 + p1;
      ls_hi += p2 + p3;
      *(float2*)&Ps[(wr + r) * PITCH + col] = make_float2(p0, p1);
      *(float2*)&Ps[(wr + r + 8) * PITCH + col] = make_float2(p2, p3);
    }
    ls_lo += __shfl_xor_sync(0xffffffffu, ls_lo, 1);
    ls_lo += __shfl_xor_sync(0xffffffffu, ls_lo, 2);
    ls_hi += __shfl_xor_sync(0xffffffffu, ls_hi, 1);
    ls_hi += __shfl_xor_sync(0xffffffffu, ls_hi, 2);
    l_lo = l_lo * corr_lo + ls_lo;
    l_hi = l_hi * corr_hi + ls_hi;
    m_lo = mn_lo;
    m_hi = mn_hi;

#pragma unroll
    for (int nt = 0; nt < 8; nt++) {
      o[nt][0] *= corr_lo;
      o[nt][1] *= corr_lo;
      o[nt][2] *= corr_hi;
      o[nt][3] *= corr_hi;
    }

    CP_WAIT(1);
    __syncthreads();

#pragma unroll
    for (int ks = 0; ks < 8; ks++) {
      uint32_t a0 = fu(Ps[(wr + r) * PITCH + ks * 8 + q]);
      uint32_t a1 = fu(Ps[(wr + r + 8) * PITCH + ks * 8 + q]);
      uint32_t a2 = fu(Ps[(wr + r) * PITCH + ks * 8 + q + 4]);
      uint32_t a3 = fu(Ps[(wr + r + 8) * PITCH + ks * 8 + q + 4]);
#pragma unroll
      for (int nt = 0; nt < 8; nt++) {
        uint32_t b0 = fu(Vs[(ks * 8 + q) * VPITCH + nt * 8 + r]);
        uint32_t b1 = fu(Vs[(ks * 8 + q + 4) * VPITCH + nt * 8 + r]);
        mma8(o[nt], a0, a1, a2, a3, b0, b1);
      }
    }
    __syncthreads();
  }

  const float il_lo = 1.0f / l_lo, il_hi = 1.0f / l_hi;
  const size_t base = ((size_t)(b * TSEQ) + q0 + wr + r) * CEMB + h * HDIM;
#pragma unroll
  for (int nt = 0; nt < 8; nt++) {
    int col = nt * 8 + 2 * q;
    float2 y0 = make_float2(o[nt][0] * il_lo, o[nt][1] * il_lo);
    float2 y1 = make_float2(o[nt][2] * il_hi, o[nt][3] * il_hi);
    y0.x = __uint_as_float(f2tf(y0.x));
    y0.y = __uint_as_float(f2tf(y0.y));
    y1.x = __uint_as_float(f2tf(y1.x));
    y1.y = __uint_as_float(f2tf(y1.y));
    *(float2*)&g_y[base + col] = y0;
    *(float2*)&g_y[base + 8 * CEMB + col] = y1;
  }
}

// ---------------------------------------------------------------------------
extern "C" void kernel_launch(void* const* d_in, const int* in_sizes, int n_in,
                              void* d_out, int out_size) {
  const float* x      = (const float*)d_in[0];
  const float* W_attn = (const float*)d_in[1];
  const float* b_attn = (const float*)d_in[2];
  const float* W_proj = (const float*)d_in[3];
  const float* b_proj = (const float*)d_in[4];
  float* out = (float*)d_out;

  float* qkv; cudaGetSymbolAddress((void**)&qkv, g_qkv);
  float* y;   cudaGetSymbolAddress((void**)&y,   g_y);
  float* xr;  cudaGetSymbolAddress((void**)&xr,  g_xr);
  float* war; cudaGetSymbolAddress((void**)&war, g_war);
  float* wpr; cudaGetSymbolAddress((void**)&wpr, g_wpr);

  const int M = BATCH * TSEQ;  // 4096

  cudaFuncSetAttribute(gemm_tf32<true>,
                       cudaFuncAttributeMaxDynamicSharedMemorySize,
                       (int)GEMM_SMEM);
  cudaFuncSetAttribute(gemm_tf32<false>,
                       cudaFuncAttributeMaxDynamicSharedMemorySize,
                       (int)GEMM_SMEM);
  cudaFuncSetAttribute(attn_tf32, cudaFuncAttributeMaxDynamicSharedMemorySize,
                       (int)ATT_SMEM);

  {
    int n4;
    n4 = (M * CEMB) / 4;
    round_tf32<<<(n4 + 255) / 256, 256>>>(x, xr, n4);
    n4 = (CEMB * C3) / 4;
    round_tf32<<<(n4 + 255) / 256, 256>>>(W_attn, war, n4);
    n4 = (CEMB * CEMB) / 4;
    round_tf32<<<(n4 + 255) / 256, 256>>>(W_proj, wpr, n4);
  }

  gemm_tf32<true><<<dim3(C3 / 128, M / 128), 128, GEMM_SMEM>>>(
      xr, war, b_attn, qkv, C3, CEMB);

  attn_tf32<<<dim3(TSEQ / 64, BATCH * NHEAD), 128, ATT_SMEM>>>();

  gemm_tf32<false><<<dim3(CEMB / 128, M / 128), 128, GEMM_SMEM>>>(
      y, wpr, b_proj, out, CEMB, CEMB);
}

// round 13
// speedup vs baseline: 1.0295x; 1.0295x over previous
#include <cuda_runtime.h>
#include <stdint.h>
#include <math.h>

#define BATCH 2
#define TSEQ  2048
#define NHEAD 12
#define HDIM  64
#define CEMB  768
#define C3    (3 * CEMB)

__device__ float g_qkv[BATCH * TSEQ * C3];    // 36 MB (tf32-rounded values)
__device__ float g_y[BATCH * TSEQ * CEMB];    // 12 MB (tf32-rounded values)
__device__ float g_xr[BATCH * TSEQ * CEMB];   // rounded x
__device__ float g_war[CEMB * C3];            // rounded W_attn
__device__ float g_wpr[CEMB * CEMB];          // rounded W_proj

__device__ __forceinline__ uint32_t f2tf(float x) {
  uint32_t r;
  asm("cvt.rna.tf32.f32 %0, %1;" : "=r"(r) : "f"(x));
  return r;
}
__device__ __forceinline__ float4 tf4(float4 v) {
  v.x = __uint_as_float(f2tf(v.x));
  v.y = __uint_as_float(f2tf(v.y));
  v.z = __uint_as_float(f2tf(v.z));
  v.w = __uint_as_float(f2tf(v.w));
  return v;
}
__device__ __forceinline__ uint32_t fu(float x) { return __float_as_uint(x); }

__device__ __forceinline__ void mma8(float* c, uint32_t a0, uint32_t a1,
                                     uint32_t a2, uint32_t a3,
                                     uint32_t b0, uint32_t b1) {
  asm volatile(
      "mma.sync.aligned.m16n8k8.row.col.f32.tf32.tf32.f32 "
      "{%0,%1,%2,%3}, {%4,%5,%6,%7}, {%8,%9}, {%0,%1,%2,%3};\n"
      : "+f"(c[0]), "+f"(c[1]), "+f"(c[2]), "+f"(c[3])
      : "r"(a0), "r"(a1), "r"(a2), "r"(a3), "r"(b0), "r"(b1));
}

__device__ __forceinline__ void cpa16(void* s, const void* g) {
  uint32_t sa = (uint32_t)__cvta_generic_to_shared(s);
  asm volatile("cp.async.cg.shared.global [%0], [%1], 16;\n" ::"r"(sa), "l"(g));
}
#define CP_COMMIT() asm volatile("cp.async.commit_group;\n")
#define CP_WAIT(n)  asm volatile("cp.async.wait_group %0;\n" ::"n"(n))

// ---------------------------------------------------------------------------
// Elementwise rna-round to tf32 pre-pass
// ---------------------------------------------------------------------------
__global__ __launch_bounds__(256) void round_tf32(const float* __restrict__ in,
                                                  float* __restrict__ out,
                                                  int n4) {
  int i = blockIdx.x * 256 + threadIdx.x;
  if (i < n4) *(float4*)&out[i * 4] = tf4(*(const float4*)&in[i * 4]);
}

// ---------------------------------------------------------------------------
// tf32 GEMM — EXACT R8 config: 4-stage cp.async, 128x128 CTA tile, BK=16,
// 256 threads (8 warps), warp tile 64x32, 128 regs, 2 CTAs/SM.
// ---------------------------------------------------------------------------
#define APITCH 20    // A-frag banks (20r+q) mod 32 all unique
#define BPITCH 136   // B-frag banks (8q+r) all unique
#define ABUF (128 * APITCH)
#define BBUF (16 * BPITCH)
#define GSTAGES 4
#define GEMM_SMEM (GSTAGES * (ABUF + BBUF) * sizeof(float))

template <bool ROUND_OUT>
__global__ __launch_bounds__(256, 2) void gemm_tf32(
    const float* __restrict__ A, const float* __restrict__ B,
    const float* __restrict__ bias, float* __restrict__ C, int N, int K) {
  extern __shared__ float sm[];
  float* As = sm;
  float* Bs = sm + GSTAGES * ABUF;

  const int tid = threadIdx.x;
  const int warp = tid >> 5, lane = tid & 31;
  const int r = lane >> 2, q = lane & 3;
  const int wm = (warp >> 2) * 64, wn = (warp & 3) * 32;
  const int bm = blockIdx.y * 128, bn = blockIdx.x * 128;

  const int ar0 = tid >> 2, ac = (tid & 3) * 4;
  const int br0 = tid >> 5, bc = (tid & 31) * 4;
  const float* Ag = A + (size_t)(bm + ar0) * K + ac;
  const float* Bg = B + (size_t)br0 * N + bn + bc;

  float acc[4][4][4];
#pragma unroll
  for (int i = 0; i < 4; i++)
#pragma unroll
    for (int j = 0; j < 4; j++)
#pragma unroll
      for (int t = 0; t < 4; t++) acc[i][j][t] = 0.0f;

  const int nk = K / 16;

#pragma unroll
  for (int i = 0; i < GSTAGES - 1; i++) {
    if (i < nk) {
      float* Ad = As + i * ABUF;
      float* Bd = Bs + i * BBUF;
      const float* Agk = Ag + i * 16;
      const float* Bgk = Bg + (size_t)i * 16 * N;
      cpa16(&Ad[ar0 * APITCH + ac], Agk);
      cpa16(&Ad[(ar0 + 64) * APITCH + ac], Agk + (size_t)64 * K);
      cpa16(&Bd[br0 * BPITCH + bc], Bgk);
      cpa16(&Bd[(br0 + 8) * BPITCH + bc], Bgk + (size_t)8 * N);
    }
    CP_COMMIT();
  }
  CP_WAIT(2);
  __syncthreads();

  for (int kb = 0; kb < nk; kb++) {
    const float* Ac = As + (kb & 3) * ABUF;
    const float* Bc = Bs + (kb & 3) * BBUF;
#pragma unroll
    for (int ks = 0; ks < 2; ks++) {
      const int k0 = ks * 8;
      uint32_t af[4][4];
#pragma unroll
      for (int mt = 0; mt < 4; mt++) {
        const float* ap = &Ac[(wm + mt * 16) * APITCH + k0];
        af[mt][0] = fu(ap[r * APITCH + q]);
        af[mt][1] = fu(ap[(r + 8) * APITCH + q]);
        af[mt][2] = fu(ap[r * APITCH + q + 4]);
        af[mt][3] = fu(ap[(r + 8) * APITCH + q + 4]);
      }
#pragma unroll
      for (int nt = 0; nt < 4; nt++) {
        uint32_t b0 = fu(Bc[(k0 + q) * BPITCH + wn + nt * 8 + r]);
        uint32_t b1 = fu(Bc[(k0 + q + 4) * BPITCH + wn + nt * 8 + r]);
#pragma unroll
        for (int mt = 0; mt < 4; mt++)
          mma8(acc[mt][nt], af[mt][0], af[mt][1], af[mt][2], af[mt][3], b0, b1);
      }
    }

    if (kb + 3 < nk) {
      int st = (kb + 3) & 3;
      float* Ad = As + st * ABUF;
      float* Bd = Bs + st * BBUF;
      const float* Agk = Ag + (kb + 3) * 16;
      const float* Bgk = Bg + (size_t)(kb + 3) * 16 * N;
      cpa16(&Ad[ar0 * APITCH + ac], Agk);
      cpa16(&Ad[(ar0 + 64) * APITCH + ac], Agk + (size_t)64 * K);
      cpa16(&Bd[br0 * BPITCH + bc], Bgk);
      cpa16(&Bd[(br0 + 8) * BPITCH + bc], Bgk + (size_t)8 * N);
    }
    CP_COMMIT();
    CP_WAIT(2);
    __syncthreads();
  }

#pragma unroll
  for (int mt = 0; mt < 4; mt++) {
    int row_lo = bm + wm + mt * 16 + r;
#pragma unroll
    for (int nt = 0; nt < 4; nt++) {
      int col = bn + wn + nt * 8 + 2 * q;
      float2 bv = *(const float2*)&bias[col];
      float2 o0 = make_float2(acc[mt][nt][0] + bv.x, acc[mt][nt][1] + bv.y);
      float2 o1 = make_float2(acc[mt][nt][2] + bv.x, acc[mt][nt][3] + bv.y);
      if (ROUND_OUT) {
        o0.x = __uint_as_float(f2tf(o0.x));
        o0.y = __uint_as_float(f2tf(o0.y));
        o1.x = __uint_as_float(f2tf(o1.x));
        o1.y = __uint_as_float(f2tf(o1.y));
      }
      *(float2*)&C[(size_t)row_lo * N + col] = o0;
      *(float2*)&C[(size_t)(row_lo + 8) * N + col] = o1;
    }
  }
}

// ---------------------------------------------------------------------------
// Flash attention, m32 warp tile: CTA = 128 queries, 4 warps x 32 rows,
// Bk=64. Each K/V b-frag feeds 2 mma (16 FLOP/B vs 8 before): smem reads
// per unit work drop 1.8x. 128 threads, 2 CTAs/SM, ~255-reg budget.
// K double-buffered, V single-buffered via cp.async (R8 schedule).
// ---------------------------------------------------------------------------
#define PITCH 68
#define VPITCH 72
#define VS_OFF (2 * 64 * PITCH)
#define PS_OFF (VS_OFF + 64 * VPITCH)
#define ATT_SMEM ((PS_OFF + 128 * PITCH) * sizeof(float))  // 88064 B

__global__ __launch_bounds__(128, 2) void attn_tf32() {
  extern __shared__ float sm[];
  float* Kb0 = sm;
  float* Kb1 = sm + 64 * PITCH;
  float* Vs  = sm + VS_OFF;
  float* Ps  = sm + PS_OFF;   // Q staging (128 rows), then P (128 rows)

  const int tid = threadIdx.x;
  const int warp = tid >> 5, lane = tid & 31;
  const int r = lane >> 2, q = lane & 3;
  const int qb = 15 - blockIdx.x;      // heavy tiles first
  const int bh = blockIdx.y;
  const int b = bh / NHEAD, h = bh % NHEAD;
  const int q0 = qb * 128;
  const float* qkv = g_qkv + (size_t)b * TSEQ * C3 + h * HDIM;

  const int rbase = tid >> 4;          // 0..7
  const int d4 = (tid & 15) << 2;

  // Stage Q (scale by 1/8 exact on tf32 values) into Ps: 128 rows
#pragma unroll
  for (int j = 0; j < 16; j++) {
    int rr = rbase + j * 8;
    float4 v = *(const float4*)&qkv[(size_t)(q0 + rr) * C3 + d4];
    v.x *= 0.125f; v.y *= 0.125f; v.z *= 0.125f; v.w *= 0.125f;
    *(float4*)&Ps[rr * PITCH + d4] = v;
  }
  // prologue: K tile 0
  {
    const float* kg = &qkv[(size_t)rbase * C3 + CEMB + d4];
#pragma unroll
    for (int j = 0; j < 8; j++)
      cpa16(&Kb0[(rbase + j * 8) * PITCH + d4], kg + (size_t)j * 8 * C3);
    CP_COMMIT();
  }
  __syncthreads();

  // Q fragments: 2 m16 tiles (rows wr+mt*16 .. +15), 8 k-steps
  const int wr = warp * 32;
  uint32_t qf[8][2][4];
#pragma unroll
  for (int ks = 0; ks < 8; ks++) {
#pragma unroll
    for (int mt = 0; mt < 2; mt++) {
      const float* ap = &Ps[(wr + mt * 16) * PITCH + ks * 8];
      qf[ks][mt][0] = fu(ap[r * PITCH + q]);
      qf[ks][mt][1] = fu(ap[(r + 8) * PITCH + q]);
      qf[ks][mt][2] = fu(ap[r * PITCH + q + 4]);
      qf[ks][mt][3] = fu(ap[(r + 8) * PITCH + q + 4]);
    }
  }
  __syncthreads();  // qf reads done before Ps reused for P

  // 4 row-group states: g = mt*2 + {0: rows ..+r, 1: rows ..+r+8}
  float mst[4], lst[4];
#pragma unroll
  for (int g = 0; g < 4; g++) { mst[g] = -1e30f; lst[g] = 0.0f; }
  float o[2][8][4];
#pragma unroll
  for (int mt = 0; mt < 2; mt++)
#pragma unroll
    for (int nt = 0; nt < 8; nt++)
#pragma unroll
      for (int t = 0; t < 4; t++) o[mt][nt][t] = 0.0f;

  const int nkt = 2 * qb + 2;

  for (int kb = 0; kb < nkt; kb++) {
    {
      const float* vg = &qkv[(size_t)(kb * 64 + rbase) * C3 + 2 * CEMB + d4];
#pragma unroll
      for (int j = 0; j < 8; j++)
        cpa16(&Vs[(rbase + j * 8) * VPITCH + d4], vg + (size_t)j * 8 * C3);
      CP_COMMIT();
    }
    if (kb + 1 < nkt) {
      float* Kn = (kb & 1) ? Kb0 : Kb1;
      const float* kg = &qkv[(size_t)((kb + 1) * 64 + rbase) * C3 + CEMB + d4];
#pragma unroll
      for (int j = 0; j < 8; j++)
        cpa16(&Kn[(rbase + j * 8) * PITCH + d4], kg + (size_t)j * 8 * C3);
    }
    CP_COMMIT();

    CP_WAIT(2);       // K(kb) arrived
    __syncthreads();

    const float* Kc = (kb & 1) ? Kb1 : Kb0;

    // S = Q K^T : each b-frag pair feeds both m-tiles
    float s[2][8][4];
#pragma unroll
    for (int mt = 0; mt < 2; mt++)
#pragma unroll
      for (int nt = 0; nt < 8; nt++)
#pragma unroll
        for (int t = 0; t < 4; t++) s[mt][nt][t] = 0.0f;
#pragma unroll
    for (int ks = 0; ks < 8; ks++) {
#pragma unroll
      for (int nt = 0; nt < 8; nt++) {
        uint32_t b0 = fu(Kc[(nt * 8 + r) * PITCH + ks * 8 + q]);
        uint32_t b1 = fu(Kc[(nt * 8 + r) * PITCH + ks * 8 + q + 4]);
        mma8(s[0][nt], qf[ks][0][0], qf[ks][0][1], qf[ks][0][2], qf[ks][0][3],
             b0, b1);
        mma8(s[1][nt], qf[ks][1][0], qf[ks][1][1], qf[ks][1][2], qf[ks][1][3],
             b0, b1);
      }
    }

    // causal mask (global coords), active only near the diagonal
    if (kb * 64 + 63 > q0 + wr) {
      const int cb = kb * 64 + 2 * q;
#pragma unroll
      for (int mt = 0; mt < 2; mt++) {
        const int row_lo = q0 + wr + mt * 16 + r, row_hi = row_lo + 8;
#pragma unroll
        for (int nt = 0; nt < 8; nt++) {
          int col = cb + nt * 8;
          if (col > row_lo) s[mt][nt][0] = -1e30f;
          if (col + 1 > row_lo) s[mt][nt][1] = -1e30f;
          if (col > row_hi) s[mt][nt][2] = -1e30f;
          if (col + 1 > row_hi) s[mt][nt][3] = -1e30f;
        }
      }
    }

    // online softmax over 4 row groups
    float mx[4];
#pragma unroll
    for (int mt = 0; mt < 2; mt++) {
      mx[mt * 2] = s[mt][0][0];
      mx[mt * 2 + 1] = s[mt][0][2];
#pragma unroll
      for (int nt = 0; nt < 8; nt++) {
        mx[mt * 2] = fmaxf(mx[mt * 2], fmaxf(s[mt][nt][0], s[mt][nt][1]));
        mx[mt * 2 + 1] =
            fmaxf(mx[mt * 2 + 1], fmaxf(s[mt][nt][2], s[mt][nt][3]));
      }
    }
#pragma unroll
    for (int g = 0; g < 4; g++) {
      mx[g] = fmaxf(mx[g], __shfl_xor_sync(0xffffffffu, mx[g], 1));
      mx[g] = fmaxf(mx[g], __shfl_xor_sync(0xffffffffu, mx[g], 2));
    }

    float mn[4], corr[4], ls[4];
#pragma unroll
    for (int g = 0; g < 4; g++) {
      mn[g] = fmaxf(mst[g], mx[g]);
      corr[g] = __expf(mst[g] - mn[g]);
      ls[g] = 0.0f;
    }

#pragma unroll
    for (int mt = 0; mt < 2; mt++) {
#pragma unroll
      for (int nt = 0; nt < 8; nt++) {
        int col = nt * 8 + 2 * q;
        float p0 = __uint_as_float(f2tf(__expf(s[mt][nt][0] - mn[mt * 2])));
        float p1 = __uint_as_float(f2tf(__expf(s[mt][nt][1] - mn[mt * 2])));
        float p2 =
            __uint_as_float(f2tf(__expf(s[mt][nt][2] - mn[mt * 2 + 1])));
        float p3 =
            __uint_as_float(f2tf(__expf(s[mt][nt][3] - mn[mt * 2 + 1])));
        ls[mt * 2] += p0 + p1;
        ls[mt * 2 + 1] += p2 + p3;
        *(float2*)&Ps[(wr + mt * 16 + r) * PITCH + col] = make_float2(p0, p1);
        *(float2*)&Ps[(wr + mt * 16 + r + 8) * PITCH + col] =
            make_float2(p2, p3);
      }
    }
#pragma unroll
    for (int g = 0; g < 4; g++) {
      ls[g] += __shfl_xor_sync(0xffffffffu, ls[g], 1);
      ls[g] += __shfl_xor_sync(0xffffffffu, ls[g], 2);
      lst[g] = lst[g] * corr[g] + ls[g];
      mst[g] = mn[g];
    }

#pragma unroll
    for (int mt = 0; mt < 2; mt++)
#pragma unroll
      for (int nt = 0; nt < 8; nt++) {
        o[mt][nt][0] *= corr[mt * 2];
        o[mt][nt][1] *= corr[mt * 2];
        o[mt][nt][2] *= corr[mt * 2 + 1];
        o[mt][nt][3] *= corr[mt * 2 + 1];
      }

    CP_WAIT(1);       // V(kb) arrived
    __syncthreads();

    // O += P V : each b-frag pair feeds both m-tiles
#pragma unroll
    for (int ks = 0; ks < 8; ks++) {
      uint32_t a[2][4];
#pragma unroll
      for (int mt = 0; mt < 2; mt++) {
        const float* pp = &Ps[(wr + mt * 16) * PITCH + ks * 8];
        a[mt][0] = fu(pp[r * PITCH + q]);
        a[mt][1] = fu(pp[(r + 8) * PITCH + q]);
        a[mt][2] = fu(pp[r * PITCH + q + 4]);
        a[mt][3] = fu(pp[(r + 8) * PITCH + q + 4]);
      }
#pragma unroll
      for (int nt = 0; nt < 8; nt++) {
        uint32_t b0 = fu(Vs[(ks * 8 + q) * VPITCH + nt * 8 + r]);
        uint32_t b1 = fu(Vs[(ks * 8 + q + 4) * VPITCH + nt * 8 + r]);
        mma8(o[0][nt], a[0][0], a[0][1], a[0][2], a[0][3], b0, b1);
        mma8(o[1][nt], a[1][0], a[1][1], a[1][2], a[1][3], b0, b1);
      }
    }
    __syncthreads();  // PV readers done before next iter's V overwrite
  }

  // epilogue: divide, round to tf32 (y feeds the proj gemm raw)
#pragma unroll
  for (int mt = 0; mt < 2; mt++) {
    const float il_lo = 1.0f / lst[mt * 2], il_hi = 1.0f / lst[mt * 2 + 1];
    const size_t base =
        ((size_t)(b * TSEQ) + q0 + wr + mt * 16 + r) * CEMB + h * HDIM;
#pragma unroll
    for (int nt = 0; nt < 8; nt++) {
      int col = nt * 8 + 2 * q;
      float2 y0 = make_float2(o[mt][nt][0] * il_lo, o[mt][nt][1] * il_lo);
      float2 y1 = make_float2(o[mt][nt][2] * il_hi, o[mt][nt][3] * il_hi);
      y0.x = __uint_as_float(f2tf(y0.x));
      y0.y = __uint_as_float(f2tf(y0.y));
      y1.x = __uint_as_float(f2tf(y1.x));
      y1.y = __uint_as_float(f2tf(y1.y));
      *(float2*)&g_y[base + col] = y0;
      *(float2*)&g_y[base + 8 * CEMB + col] = y1;
    }
  }
}

// ---------------------------------------------------------------------------
extern "C" void kernel_launch(void* const* d_in, const int* in_sizes, int n_in,
                              void* d_out, int out_size) {
  const float* x      = (const float*)d_in[0];
  const float* W_attn = (const float*)d_in[1];
  const float* b_attn = (const float*)d_in[2];
  const float* W_proj = (const float*)d_in[3];
  const float* b_proj = (const float*)d_in[4];
  float* out = (float*)d_out;

  float* qkv; cudaGetSymbolAddress((void**)&qkv, g_qkv);
  float* y;   cudaGetSymbolAddress((void**)&y,   g_y);
  float* xr;  cudaGetSymbolAddress((void**)&xr,  g_xr);
  float* war; cudaGetSymbolAddress((void**)&war, g_war);
  float* wpr; cudaGetSymbolAddress((void**)&wpr, g_wpr);

  const int M = BATCH * TSEQ;  // 4096

  cudaFuncSetAttribute(gemm_tf32<true>,
                       cudaFuncAttributeMaxDynamicSharedMemorySize,
                       (int)GEMM_SMEM);
  cudaFuncSetAttribute(gemm_tf32<false>,
                       cudaFuncAttributeMaxDynamicSharedMemorySize,
                       (int)GEMM_SMEM);
  cudaFuncSetAttribute(attn_tf32, cudaFuncAttributeMaxDynamicSharedMemorySize,
                       (int)ATT_SMEM);

  {
    int n4;
    n4 = (M * CEMB) / 4;
    round_tf32<<<(n4 + 255) / 256, 256>>>(x, xr, n4);
    n4 = (CEMB * C3) / 4;
    round_tf32<<<(n4 + 255) / 256, 256>>>(W_attn, war, n4);
    n4 = (CEMB * CEMB) / 4;
    round_tf32<<<(n4 + 255) / 256, 256>>>(W_proj, wpr, n4);
  }

  gemm_tf32<true><<<dim3(C3 / 128, M / 128), 256, GEMM_SMEM>>>(
      xr, war, b_attn, qkv, C3, CEMB);

  attn_tf32<<<dim3(TSEQ / 128, BATCH * NHEAD), 128, ATT_SMEM>>>();

  gemm_tf32<false><<<dim3(CEMB / 128, M / 128), 256, GEMM_SMEM>>>(
      y, wpr, b_proj, out, CEMB, CEMB);
}

// round 17
// speedup vs baseline: 1.0532x; 1.0230x over previous
#include <cuda_runtime.h>
#include <stdint.h>
#include <math.h>

#define BATCH 2
#define TSEQ  2048
#define NHEAD 12
#define HDIM  64
#define CEMB  768
#define C3    (3 * CEMB)

__device__ float g_qkv[BATCH * TSEQ * C3];    // 36 MB (tf32-rounded values)
__device__ float g_y[BATCH * TSEQ * CEMB];    // 12 MB (tf32-rounded values)
__device__ float g_xr[BATCH * TSEQ * CEMB];   // rounded x
__device__ float g_war[CEMB * C3];            // rounded W_attn
__device__ float g_wpr[CEMB * CEMB];          // rounded W_proj

__device__ __forceinline__ uint32_t f2tf(float x) {
  uint32_t r;
  asm("cvt.rna.tf32.f32 %0, %1;" : "=r"(r) : "f"(x));
  return r;
}
__device__ __forceinline__ float4 tf4(float4 v) {
  v.x = __uint_as_float(f2tf(v.x));
  v.y = __uint_as_float(f2tf(v.y));
  v.z = __uint_as_float(f2tf(v.z));
  v.w = __uint_as_float(f2tf(v.w));
  return v;
}
__device__ __forceinline__ uint32_t fu(float x) { return __float_as_uint(x); }

__device__ __forceinline__ void mma8(float* c, uint32_t a0, uint32_t a1,
                                     uint32_t a2, uint32_t a3,
                                     uint32_t b0, uint32_t b1) {
  asm volatile(
      "mma.sync.aligned.m16n8k8.row.col.f32.tf32.tf32.f32 "
      "{%0,%1,%2,%3}, {%4,%5,%6,%7}, {%8,%9}, {%0,%1,%2,%3};\n"
      : "+f"(c[0]), "+f"(c[1]), "+f"(c[2]), "+f"(c[3])
      : "r"(a0), "r"(a1), "r"(a2), "r"(a3), "r"(b0), "r"(b1));
}

__device__ __forceinline__ void cpa16(void* s, const void* g) {
  uint32_t sa = (uint32_t)__cvta_generic_to_shared(s);
  asm volatile("cp.async.cg.shared.global [%0], [%1], 16;\n" ::"r"(sa), "l"(g));
}
#define CP_COMMIT() asm volatile("cp.async.commit_group;\n")
#define CP_WAIT(n)  asm volatile("cp.async.wait_group %0;\n" ::"n"(n))

// ---------------------------------------------------------------------------
// Elementwise rna-round to tf32 pre-pass
// ---------------------------------------------------------------------------
__global__ __launch_bounds__(256) void round_tf32(const float* __restrict__ in,
                                                  float* __restrict__ out,
                                                  int n4) {
  int i = blockIdx.x * 256 + threadIdx.x;
  if (i < n4) *(float4*)&out[i * 4] = tf4(*(const float4*)&in[i * 4]);
}

// ---------------------------------------------------------------------------
// tf32 GEMM — EXACT R8 config: 4-stage cp.async, 128x128 CTA tile, BK=16,
// 256 threads (8 warps), warp tile 64x32, 128 regs, 2 CTAs/SM.
// ---------------------------------------------------------------------------
#define APITCH 20    // A-frag banks (20r+q) mod 32 all unique
#define BPITCH 136   // B-frag banks (8q+r) all unique
#define ABUF (128 * APITCH)
#define BBUF (16 * BPITCH)
#define GSTAGES 4
#define GEMM_SMEM (GSTAGES * (ABUF + BBUF) * sizeof(float))

template <bool ROUND_OUT>
__global__ __launch_bounds__(256, 2) void gemm_tf32(
    const float* __restrict__ A, const float* __restrict__ B,
    const float* __restrict__ bias, float* __restrict__ C, int N, int K) {
  extern __shared__ float sm[];
  float* As = sm;
  float* Bs = sm + GSTAGES * ABUF;

  const int tid = threadIdx.x;
  const int warp = tid >> 5, lane = tid & 31;
  const int r = lane >> 2, q = lane & 3;
  const int wm = (warp >> 2) * 64, wn = (warp & 3) * 32;
  const int bm = blockIdx.y * 128, bn = blockIdx.x * 128;

  const int ar0 = tid >> 2, ac = (tid & 3) * 4;
  const int br0 = tid >> 5, bc = (tid & 31) * 4;
  const float* Ag = A + (size_t)(bm + ar0) * K + ac;
  const float* Bg = B + (size_t)br0 * N + bn + bc;

  float acc[4][4][4];
#pragma unroll
  for (int i = 0; i < 4; i++)
#pragma unroll
    for (int j = 0; j < 4; j++)
#pragma unroll
      for (int t = 0; t < 4; t++) acc[i][j][t] = 0.0f;

  const int nk = K / 16;

#pragma unroll
  for (int i = 0; i < GSTAGES - 1; i++) {
    if (i < nk) {
      float* Ad = As + i * ABUF;
      float* Bd = Bs + i * BBUF;
      const float* Agk = Ag + i * 16;
      const float* Bgk = Bg + (size_t)i * 16 * N;
      cpa16(&Ad[ar0 * APITCH + ac], Agk);
      cpa16(&Ad[(ar0 + 64) * APITCH + ac], Agk + (size_t)64 * K);
      cpa16(&Bd[br0 * BPITCH + bc], Bgk);
      cpa16(&Bd[(br0 + 8) * BPITCH + bc], Bgk + (size_t)8 * N);
    }
    CP_COMMIT();
  }
  CP_WAIT(2);
  __syncthreads();

  for (int kb = 0; kb < nk; kb++) {
    const float* Ac = As + (kb & 3) * ABUF;
    const float* Bc = Bs + (kb & 3) * BBUF;
#pragma unroll
    for (int ks = 0; ks < 2; ks++) {
      const int k0 = ks * 8;
      uint32_t af[4][4];
#pragma unroll
      for (int mt = 0; mt < 4; mt++) {
        const float* ap = &Ac[(wm + mt * 16) * APITCH + k0];
        af[mt][0] = fu(ap[r * APITCH + q]);
        af[mt][1] = fu(ap[(r + 8) * APITCH + q]);
        af[mt][2] = fu(ap[r * APITCH + q + 4]);
        af[mt][3] = fu(ap[(r + 8) * APITCH + q + 4]);
      }
#pragma unroll
      for (int nt = 0; nt < 4; nt++) {
        uint32_t b0 = fu(Bc[(k0 + q) * BPITCH + wn + nt * 8 + r]);
        uint32_t b1 = fu(Bc[(k0 + q + 4) * BPITCH + wn + nt * 8 + r]);
#pragma unroll
        for (int mt = 0; mt < 4; mt++)
          mma8(acc[mt][nt], af[mt][0], af[mt][1], af[mt][2], af[mt][3], b0, b1);
      }
    }

    if (kb + 3 < nk) {
      int st = (kb + 3) & 3;
      float* Ad = As + st * ABUF;
      float* Bd = Bs + st * BBUF;
      const float* Agk = Ag + (kb + 3) * 16;
      const float* Bgk = Bg + (size_t)(kb + 3) * 16 * N;
      cpa16(&Ad[ar0 * APITCH + ac], Agk);
      cpa16(&Ad[(ar0 + 64) * APITCH + ac], Agk + (size_t)64 * K);
      cpa16(&Bd[br0 * BPITCH + bc], Bgk);
      cpa16(&Bd[(br0 + 8) * BPITCH + bc], Bgk + (size_t)8 * N);
    }
    CP_COMMIT();
    CP_WAIT(2);
    __syncthreads();
  }

#pragma unroll
  for (int mt = 0; mt < 4; mt++) {
    int row_lo = bm + wm + mt * 16 + r;
#pragma unroll
    for (int nt = 0; nt < 4; nt++) {
      int col = bn + wn + nt * 8 + 2 * q;
      float2 bv = *(const float2*)&bias[col];
      float2 o0 = make_float2(acc[mt][nt][0] + bv.x, acc[mt][nt][1] + bv.y);
      float2 o1 = make_float2(acc[mt][nt][2] + bv.x, acc[mt][nt][3] + bv.y);
      if (ROUND_OUT) {
        o0.x = __uint_as_float(f2tf(o0.x));
        o0.y = __uint_as_float(f2tf(o0.y));
        o1.x = __uint_as_float(f2tf(o1.x));
        o1.y = __uint_as_float(f2tf(o1.y));
      }
      *(float2*)&C[(size_t)row_lo * N + col] = o0;
      *(float2*)&C[(size_t)(row_lo + 8) * N + col] = o1;
    }
  }
}

// ---------------------------------------------------------------------------
// Flash attention, m16 warp tile (R8 base), NO P smem round-trip:
// S c-frag -> PV a-frag via warp shfl transpose. K and V both double-buffered,
// one cp.async group per iter (G_j = {K(j+2), V(j+1)}), CP_WAIT(1), and only
// TWO barriers per iter. 64q/CTA, 4 warps, 3 CTAs/SM.
// ---------------------------------------------------------------------------
#define PITCH 68
#define VPITCH 72
#define KBUF (64 * PITCH)
#define VBUF (64 * VPITCH)
// layout: K0, K1, V0, V1
#define ATT_SMEM ((2 * KBUF + 2 * VBUF) * sizeof(float))  // 71680 B

__global__ __launch_bounds__(128, 3) void attn_tf32() {
  extern __shared__ float sm[];
  float* Kb0 = sm;
  float* Kb1 = sm + KBUF;
  float* Vb0 = sm + 2 * KBUF;
  float* Vb1 = sm + 2 * KBUF + VBUF;

  const int tid = threadIdx.x;
  const int warp = tid >> 5, lane = tid & 31;
  const int r = lane >> 2, q = lane & 3;
  const int qb = 31 - blockIdx.x;  // heavy tiles first
  const int bh = blockIdx.y;
  const int b = bh / NHEAD, h = bh % NHEAD;
  const int q0 = qb * 64;
  const float* qkv = g_qkv + (size_t)b * TSEQ * C3 + h * HDIM;

  const int rbase = tid >> 4;
  const int d4 = (tid & 15) << 2;

  // Prologue: K(0) in flight while Q stages through V0.
  {
    const float* kg = &qkv[(size_t)rbase * C3 + CEMB + d4];
#pragma unroll
    for (int j = 0; j < 8; j++)
      cpa16(&Kb0[(rbase + j * 8) * PITCH + d4], kg + (size_t)j * 8 * C3);
    CP_COMMIT();  // G_{-2} = {K(0)}
  }
  // Stage Q (scale 1/8 exact on tf32 values) into V0
#pragma unroll
  for (int j = 0; j < 8; j++) {
    int rr = rbase + j * 8;
    float4 v = *(const float4*)&qkv[(size_t)(q0 + rr) * C3 + d4];
    v.x *= 0.125f; v.y *= 0.125f; v.z *= 0.125f; v.w *= 0.125f;
    *(float4*)&Vb0[rr * VPITCH + d4] = v;
  }
  __syncthreads();

  uint32_t qf[8][4];
  const int wr = warp * 16;
#pragma unroll
  for (int ks = 0; ks < 8; ks++) {
    const float* ap = &Vb0[wr * VPITCH + ks * 8];
    qf[ks][0] = fu(ap[r * VPITCH + q]);
    qf[ks][1] = fu(ap[(r + 8) * VPITCH + q]);
    qf[ks][2] = fu(ap[r * VPITCH + q + 4]);
    qf[ks][3] = fu(ap[(r + 8) * VPITCH + q + 4]);
  }
  __syncthreads();  // qf reads done before V(0) lands in V0

  // G_{-1} = {K(1), V(0)}
  {
    if (qb >= 1) {
      const float* kg = &qkv[(size_t)(64 + rbase) * C3 + CEMB + d4];
#pragma unroll
      for (int j = 0; j < 8; j++)
        cpa16(&Kb1[(rbase + j * 8) * PITCH + d4], kg + (size_t)j * 8 * C3);
    }
    const float* vg = &qkv[(size_t)rbase * C3 + 2 * CEMB + d4];
#pragma unroll
    for (int j = 0; j < 8; j++)
      cpa16(&Vb0[(rbase + j * 8) * VPITCH + d4], vg + (size_t)j * 8 * C3);
    CP_COMMIT();
  }
  CP_WAIT(1);       // K(0) done
  __syncthreads();  // K(0) visible

  float m_lo = -1e30f, m_hi = -1e30f, l_lo = 0.0f, l_hi = 0.0f;
  float o[8][4];
#pragma unroll
  for (int nt = 0; nt < 8; nt++)
#pragma unroll
    for (int t = 0; t < 4; t++) o[nt][t] = 0.0f;

  const int srcA = (lane & ~3) | (q >> 1);  // 4r + (q>>1)
  const int srcB = srcA + 2;
  const bool odd = (q & 1) != 0;

  for (int kb = 0; kb <= qb; kb++) {
    const float* Kc = (kb & 1) ? Kb1 : Kb0;

    // S = Q K^T
    float s[8][4];
#pragma unroll
    for (int nt = 0; nt < 8; nt++)
#pragma unroll
      for (int t = 0; t < 4; t++) s[nt][t] = 0.0f;
#pragma unroll
    for (int ks = 0; ks < 8; ks++) {
#pragma unroll
      for (int nt = 0; nt < 8; nt++) {
        uint32_t b0 = fu(Kc[(nt * 8 + r) * PITCH + ks * 8 + q]);
        uint32_t b1 = fu(Kc[(nt * 8 + r) * PITCH + ks * 8 + q + 4]);
        mma8(s[nt], qf[ks][0], qf[ks][1], qf[ks][2], qf[ks][3], b0, b1);
      }
    }

    __syncthreads();  // all warps done reading K^cur -> safe to overwrite

    // issue G_kb = {K(kb+2) -> K^cur, V(kb+1) -> V^{(kb+1)&1}}
    if (kb + 2 <= qb) {
      float* Kn = (kb & 1) ? Kb1 : Kb0;
      const float* kg = &qkv[(size_t)((kb + 2) * 64 + rbase) * C3 + CEMB + d4];
#pragma unroll
      for (int j = 0; j < 8; j++)
        cpa16(&Kn[(rbase + j * 8) * PITCH + d4], kg + (size_t)j * 8 * C3);
    }
    if (kb + 1 <= qb) {
      float* Vn = ((kb + 1) & 1) ? Vb1 : Vb0;
      const float* vg =
          &qkv[(size_t)((kb + 1) * 64 + rbase) * C3 + 2 * CEMB + d4];
#pragma unroll
      for (int j = 0; j < 8; j++)
        cpa16(&Vn[(rbase + j * 8) * VPITCH + d4], vg + (size_t)j * 8 * C3);
    }
    CP_COMMIT();

    // causal mask on diagonal tile (local coords)
    if (kb == qb) {
      const int row_lo = wr + r, row_hi = row_lo + 8;
#pragma unroll
      for (int nt = 0; nt < 8; nt++) {
        int col = nt * 8 + 2 * q;
        if (col > row_lo) s[nt][0] = -1e30f;
        if (col + 1 > row_lo) s[nt][1] = -1e30f;
        if (col > row_hi) s[nt][2] = -1e30f;
        if (col + 1 > row_hi) s[nt][3] = -1e30f;
      }
    }

    // online softmax (p kept in registers; no smem)
    float mx_lo = s[0][0], mx_hi = s[0][2];
#pragma unroll
    for (int nt = 0; nt < 8; nt++) {
      mx_lo = fmaxf(mx_lo, fmaxf(s[nt][0], s[nt][1]));
      mx_hi = fmaxf(mx_hi, fmaxf(s[nt][2], s[nt][3]));
    }
    mx_lo = fmaxf(mx_lo, __shfl_xor_sync(0xffffffffu, mx_lo, 1));
    mx_lo = fmaxf(mx_lo, __shfl_xor_sync(0xffffffffu, mx_lo, 2));
    mx_hi = fmaxf(mx_hi, __shfl_xor_sync(0xffffffffu, mx_hi, 1));
    mx_hi = fmaxf(mx_hi, __shfl_xor_sync(0xffffffffu, mx_hi, 2));

    float mn_lo = fmaxf(m_lo, mx_lo), mn_hi = fmaxf(m_hi, mx_hi);
    float corr_lo = __expf(m_lo - mn_lo), corr_hi = __expf(m_hi - mn_hi);

    float ls_lo = 0.0f, ls_hi = 0.0f;
#pragma unroll
    for (int nt = 0; nt < 8; nt++) {
      float p0 = __uint_as_float(f2tf(__expf(s[nt][0] - mn_lo)));
      float p1 = __uint_as_float(f2tf(__expf(s[nt][1] - mn_lo)));
      float p2 = __uint_as_float(f2tf(__expf(s[nt][2] - mn_hi)));
      float p3 = __uint_as_float(f2tf(__expf(s[nt][3] - mn_hi)));
      ls_lo += p0 + p1;
      ls_hi += p2 + p3;
      s[nt][0] = p0; s[nt][1] = p1; s[nt][2] = p2; s[nt][3] = p3;
    }
    ls_lo += __shfl_xor_sync(0xffffffffu, ls_lo, 1);
    ls_lo += __shfl_xor_sync(0xffffffffu, ls_lo, 2);
    ls_hi += __shfl_xor_sync(0xffffffffu, ls_hi, 1);
    ls_hi += __shfl_xor_sync(0xffffffffu, ls_hi, 2);
    l_lo = l_lo * corr_lo + ls_lo;
    l_hi = l_hi * corr_hi + ls_hi;
    m_lo = mn_lo;
    m_hi = mn_hi;

#pragma unroll
    for (int nt = 0; nt < 8; nt++) {
      o[nt][0] *= corr_lo;
      o[nt][1] *= corr_lo;
      o[nt][2] *= corr_hi;
      o[nt][3] *= corr_hi;
    }

    CP_WAIT(1);       // V(kb) arrived (only G_kb may remain in flight)
    __syncthreads();  // V(kb) visible to all warps

    const float* Vc = (kb & 1) ? Vb1 : Vb0;

    // O += P V : a-frag built from S c-frag via shfl transpose.
    // value (row R, col C) of k-block ks lives at lane 4R+(C>>1),
    // slot (C&1) [+2 for row R+8]. Target lane 4r+q needs cols q, q+4.
#pragma unroll
    for (int ks = 0; ks < 8; ks++) {
      float e0 = __shfl_sync(0xffffffffu, s[ks][0], srcA);
      float e1 = __shfl_sync(0xffffffffu, s[ks][1], srcA);
      float g0 = __shfl_sync(0xffffffffu, s[ks][2], srcA);
      float g1 = __shfl_sync(0xffffffffu, s[ks][3], srcA);
      float f0 = __shfl_sync(0xffffffffu, s[ks][0], srcB);
      float f1 = __shfl_sync(0xffffffffu, s[ks][1], srcB);
      float h0 = __shfl_sync(0xffffffffu, s[ks][2], srcB);
      float h1 = __shfl_sync(0xffffffffu, s[ks][3], srcB);
      uint32_t a0 = fu(odd ? e1 : e0);
      uint32_t a1 = fu(odd ? g1 : g0);
      uint32_t a2 = fu(odd ? f1 : f0);
      uint32_t a3 = fu(odd ? h1 : h0);
#pragma unroll
      for (int nt = 0; nt < 8; nt++) {
        uint32_t b0 = fu(Vc[(ks * 8 + q) * VPITCH + nt * 8 + r]);
        uint32_t b1 = fu(Vc[(ks * 8 + q + 4) * VPITCH + nt * 8 + r]);
        mma8(o[nt], a0, a1, a2, a3, b0, b1);
      }
    }
    // no trailing barrier: V^cur is only overwritten by V(kb+2), issued
    // next iter AFTER the post-S barrier (which follows this PV in program
    // order for every thread).
  }

  const float il_lo = 1.0f / l_lo, il_hi = 1.0f / l_hi;
  const size_t base = ((size_t)(b * TSEQ) + q0 + wr + r) * CEMB + h * HDIM;
#pragma unroll
  for (int nt = 0; nt < 8; nt++) {
    int col = nt * 8 + 2 * q;
    float2 y0 = make_float2(o[nt][0] * il_lo, o[nt][1] * il_lo);
    float2 y1 = make_float2(o[nt][2] * il_hi, o[nt][3] * il_hi);
    y0.x = __uint_as_float(f2tf(y0.x));
    y0.y = __uint_as_float(f2tf(y0.y));
    y1.x = __uint_as_float(f2tf(y1.x));
    y1.y = __uint_as_float(f2tf(y1.y));
    *(float2*)&g_y[base + col] = y0;
    *(float2*)&g_y[base + 8 * CEMB + col] = y1;
  }
}

// ---------------------------------------------------------------------------
extern "C" void kernel_launch(void* const* d_in, const int* in_sizes, int n_in,
                              void* d_out, int out_size) {
  const float* x      = (const float*)d_in[0];
  const float* W_attn = (const float*)d_in[1];
  const float* b_attn = (const float*)d_in[2];
  const float* W_proj = (const float*)d_in[3];
  const float* b_proj = (const float*)d_in[4];
  float* out = (float*)d_out;

  float* qkv; cudaGetSymbolAddress((void**)&qkv, g_qkv);
  float* y;   cudaGetSymbolAddress((void**)&y,   g_y);
  float* xr;  cudaGetSymbolAddress((void**)&xr,  g_xr);
  float* war; cudaGetSymbolAddress((void**)&war, g_war);
  float* wpr; cudaGetSymbolAddress((void**)&wpr, g_wpr);

  const int M = BATCH * TSEQ;  // 4096

  cudaFuncSetAttribute(gemm_tf32<true>,
                       cudaFuncAttributeMaxDynamicSharedMemorySize,
                       (int)GEMM_SMEM);
  cudaFuncSetAttribute(gemm_tf32<false>,
                       cudaFuncAttributeMaxDynamicSharedMemorySize,
                       (int)GEMM_SMEM);
  cudaFuncSetAttribute(attn_tf32, cudaFuncAttributeMaxDynamicSharedMemorySize,
                       (int)ATT_SMEM);

  {
    int n4;
    n4 = (M * CEMB) / 4;
    round_tf32<<<(n4 + 255) / 256, 256>>>(x, xr, n4);
    n4 = (CEMB * C3) / 4;
    round_tf32<<<(n4 + 255) / 256, 256>>>(W_attn, war, n4);
    n4 = (CEMB * CEMB) / 4;
    round_tf32<<<(n4 + 255) / 256, 256>>>(W_proj, wpr, n4);
  }

  gemm_tf32<true><<<dim3(C3 / 128, M / 128), 256, GEMM_SMEM>>>(
      xr, war, b_attn, qkv, C3, CEMB);

  attn_tf32<<<dim3(TSEQ / 64, BATCH * NHEAD), 128, ATT_SMEM>>>();

  gemm_tf32<false><<<dim3(CEMB / 128, M / 128), 256, GEMM_SMEM>>>(
      y, wpr, b_proj, out, CEMB, CEMB);
}